// round 2
// baseline (speedup 1.0000x reference)
#include <cuda_runtime.h>

#define B_ 2
#define L_ 4096
#define H_ 1024

// Scratch (allowed: __device__ globals, no runtime allocation)
__device__ float g_h[B_ * L_ * H_];   // RoPE'd hidden states, 33.5 MB
__device__ float g_G[B_ * H_ * H_];   // h^T h per batch, 8 MB
__device__ float g_M[B_ * H_ * H_];   // W_q^T G per batch, 8 MB

// ---------------------------------------------------------------------------
// RoPE: h = x * cos + rotate_half(x) * sin   (rotate_half: [-x2, x1])
// One float4 per thread; half-dim boundary (512) is float4-aligned.
// ---------------------------------------------------------------------------
__global__ void rope_kernel(const float* __restrict__ x,
                            const float* __restrict__ cs,
                            const float* __restrict__ sn,
                            float* __restrict__ h) {
    long idx4 = (long)blockIdx.x * blockDim.x + threadIdx.x;
    long e = idx4 * 4;                       // element index into [B,L,H]
    int c = (int)(e & (H_ - 1));             // channel
    int l = (int)((e >> 10) & (L_ - 1));     // position (H_=1024 -> >>10)

    float4 xv = *(const float4*)(x + e);
    float4 cv = *(const float4*)(cs + (long)l * H_ + c);
    float4 sv = *(const float4*)(sn + (long)l * H_ + c);
    float4 rv;
    if (c < H_ / 2) {
        float4 t = *(const float4*)(x + e + H_ / 2);
        rv.x = -t.x; rv.y = -t.y; rv.z = -t.z; rv.w = -t.w;
    } else {
        rv = *(const float4*)(x + e - H_ / 2);
    }
    float4 o;
    o.x = xv.x * cv.x + rv.x * sv.x;
    o.y = xv.y * cv.y + rv.y * sv.y;
    o.z = xv.z * cv.z + rv.z * sv.z;
    o.w = xv.w * cv.w + rv.w * sv.w;
    *(float4*)(h + e) = o;
}

// ---------------------------------------------------------------------------
// TN GEMM: C[m,n] = sum_k A[k,m] * B[k,n]   (both operands K-major row layout)
// 128x128 block, K-tile 16, 256 threads, 8x8 per-thread microtile.
// Dims assumed multiples of 128 (M,N) and 16 (K).
// ---------------------------------------------------------------------------
__global__ __launch_bounds__(256, 2)
void gemm_tn(const float* __restrict__ Ab, const float* __restrict__ Bb,
             float* __restrict__ Cb, int Kdim,
             int lda, int ldb, int ldc,
             long sA, long sB, long sC) {
    const float* A = Ab + (long)blockIdx.z * sA;
    const float* Bm = Bb + (long)blockIdx.z * sB;
    float* C = Cb + (long)blockIdx.z * sC;

    __shared__ float As[16][128];
    __shared__ float Bs[16][128];

    int tid = threadIdx.x;
    int m0 = blockIdx.y * 128, n0 = blockIdx.x * 128;
    int ty = tid >> 4, tx = tid & 15;

    int lr = tid >> 5;              // k-row within tile (t=0), +8 for t=1
    int lc = (tid & 31) << 2;       // column (float4)

    float acc[8][8];
#pragma unroll
    for (int i = 0; i < 8; i++)
#pragma unroll
        for (int j = 0; j < 8; j++) acc[i][j] = 0.f;

    for (int k0 = 0; k0 < Kdim; k0 += 16) {
        *(float4*)&As[lr][lc]     = *(const float4*)&A[(long)(k0 + lr) * lda + m0 + lc];
        *(float4*)&As[lr + 8][lc] = *(const float4*)&A[(long)(k0 + lr + 8) * lda + m0 + lc];
        *(float4*)&Bs[lr][lc]     = *(const float4*)&Bm[(long)(k0 + lr) * ldb + n0 + lc];
        *(float4*)&Bs[lr + 8][lc] = *(const float4*)&Bm[(long)(k0 + lr + 8) * ldb + n0 + lc];
        __syncthreads();
#pragma unroll
        for (int kk = 0; kk < 16; kk++) {
            float a[8], b[8];
            *(float4*)(a)     = *(float4*)&As[kk][ty * 8];
            *(float4*)(a + 4) = *(float4*)&As[kk][ty * 8 + 4];
            *(float4*)(b)     = *(float4*)&Bs[kk][tx * 8];
            *(float4*)(b + 4) = *(float4*)&Bs[kk][tx * 8 + 4];
#pragma unroll
            for (int i = 0; i < 8; i++)
#pragma unroll
                for (int j = 0; j < 8; j++) acc[i][j] += a[i] * b[j];
        }
        __syncthreads();
    }

#pragma unroll
    for (int i = 0; i < 8; i++) {
        long row = m0 + ty * 8 + i;
        float4 v0 = make_float4(acc[i][0], acc[i][1], acc[i][2], acc[i][3]);
        float4 v1 = make_float4(acc[i][4], acc[i][5], acc[i][6], acc[i][7]);
        *(float4*)&C[row * ldc + n0 + tx * 8]     = v0;
        *(float4*)&C[row * ldc + n0 + tx * 8 + 4] = v1;
    }
}

// ---------------------------------------------------------------------------
// NN GEMM: C[m,n] = sum_k A[m,k] * B[k,n]   (A row-major [M,K], B row-major [K,N])
// Same tiling; A tile transposed into smem on load.
// ---------------------------------------------------------------------------
__global__ __launch_bounds__(256, 2)
void gemm_nn(const float* __restrict__ Ab, const float* __restrict__ Bb,
             float* __restrict__ Cb, int Kdim,
             int lda, int ldb, int ldc,
             long sA, long sB, long sC) {
    const float* A = Ab + (long)blockIdx.z * sA;
    const float* Bm = Bb + (long)blockIdx.z * sB;
    float* C = Cb + (long)blockIdx.z * sC;

    __shared__ float As[16][128];   // stored transposed: As[k][m]
    __shared__ float Bs[16][128];

    int tid = threadIdx.x;
    int m0 = blockIdx.y * 128, n0 = blockIdx.x * 128;
    int ty = tid >> 4, tx = tid & 15;

    int ar = tid >> 2;              // A row within tile (t=0), +64 for t=1
    int ac = (tid & 3) << 2;        // A col (float4)
    int br = tid >> 5;              // B k-row (t=0), +8 for t=1
    int bc = (tid & 31) << 2;       // B col (float4)

    float acc[8][8];
#pragma unroll
    for (int i = 0; i < 8; i++)
#pragma unroll
        for (int j = 0; j < 8; j++) acc[i][j] = 0.f;

    for (int k0 = 0; k0 < Kdim; k0 += 16) {
        float4 va0 = *(const float4*)&A[(long)(m0 + ar) * lda + k0 + ac];
        float4 va1 = *(const float4*)&A[(long)(m0 + ar + 64) * lda + k0 + ac];
        As[ac + 0][ar] = va0.x; As[ac + 1][ar] = va0.y;
        As[ac + 2][ar] = va0.z; As[ac + 3][ar] = va0.w;
        As[ac + 0][ar + 64] = va1.x; As[ac + 1][ar + 64] = va1.y;
        As[ac + 2][ar + 64] = va1.z; As[ac + 3][ar + 64] = va1.w;
        *(float4*)&Bs[br][bc]     = *(const float4*)&Bm[(long)(k0 + br) * ldb + n0 + bc];
        *(float4*)&Bs[br + 8][bc] = *(const float4*)&Bm[(long)(k0 + br + 8) * ldb + n0 + bc];
        __syncthreads();
#pragma unroll
        for (int kk = 0; kk < 16; kk++) {
            float a[8], b[8];
            *(float4*)(a)     = *(float4*)&As[kk][ty * 8];
            *(float4*)(a + 4) = *(float4*)&As[kk][ty * 8 + 4];
            *(float4*)(b)     = *(float4*)&Bs[kk][tx * 8];
            *(float4*)(b + 4) = *(float4*)&Bs[kk][tx * 8 + 4];
#pragma unroll
            for (int i = 0; i < 8; i++)
#pragma unroll
                for (int j = 0; j < 8; j++) acc[i][j] += a[i] * b[j];
        }
        __syncthreads();
    }

#pragma unroll
    for (int i = 0; i < 8; i++) {
        long row = m0 + ty * 8 + i;
        float4 v0 = make_float4(acc[i][0], acc[i][1], acc[i][2], acc[i][3]);
        float4 v1 = make_float4(acc[i][4], acc[i][5], acc[i][6], acc[i][7]);
        *(float4*)&C[row * ldc + n0 + tx * 8]     = v0;
        *(float4*)&C[row * ldc + n0 + tx * 8 + 4] = v1;
    }
}

// ---------------------------------------------------------------------------
// Launch: out_b = h_b @ (W_q^T @ (h_b^T @ h_b))   -- exact reassociation of
// ((h W_q^T) h^T) h, avoiding the [B,L,L] intermediate entirely.
// ---------------------------------------------------------------------------
extern "C" void kernel_launch(void* const* d_in, const int* in_sizes, int n_in,
                              void* d_out, int out_size) {
    const float* x  = (const float*)d_in[0];   // hidden_states [B,L,H]
    const float* W  = (const float*)d_in[1];   // W_q [H,H]
    const float* cs = (const float*)d_in[2];   // cos [L,H]
    const float* sn = (const float*)d_in[3];   // sin [L,H]
    float* out = (float*)d_out;                // [B,L,H]

    void *ph, *pG, *pM;
    cudaGetSymbolAddress(&ph, g_h);
    cudaGetSymbolAddress(&pG, g_G);
    cudaGetSymbolAddress(&pM, g_M);
    float* h = (float*)ph;
    float* G = (float*)pG;
    float* Mb = (float*)pM;

    const long sBatchH = (long)L_ * H_;   // 4194304
    const long sBatchG = (long)H_ * H_;   // 1048576

    // 1) RoPE
    rope_kernel<<<(B_ * L_ * H_ / 4) / 256, 256>>>(x, cs, sn, h);

    // 2) G_b = h_b^T h_b    [1024 x 1024, K = 4096]
    {
        dim3 grid(H_ / 128, H_ / 128, B_);
        gemm_tn<<<grid, 256>>>(h, h, G, L_, H_, H_, H_, sBatchH, sBatchH, sBatchG);
    }

    // 3) M_b = W_q^T G_b    [1024 x 1024, K = 1024]  (W shared across batch)
    {
        dim3 grid(H_ / 128, H_ / 128, B_);
        gemm_tn<<<grid, 256>>>(W, G, Mb, H_, H_, H_, H_, 0L, sBatchG, sBatchG);
    }

    // 4) out_b = h_b M_b    [4096 x 1024, K = 1024]
    {
        dim3 grid(H_ / 128, L_ / 128, B_);
        gemm_nn<<<grid, 256>>>(h, Mb, out, H_, H_, H_, H_, sBatchH, sBatchG, sBatchH);
    }
}

// round 4
// speedup vs baseline: 2.3194x; 2.3194x over previous
#include <cuda_runtime.h>
#include <cuda_bf16.h>
#include <cstdint>

#define B_ 2
#define L_ 4096
#define H_ 1024

typedef __nv_bfloat16 bf16;

// ---------------- scratch (__device__ globals; no runtime alloc) ------------
__device__ bf16 g_h_hi [B_ * L_ * H_];   // RoPE'd h, bf16 hi   [B][L][H]
__device__ bf16 g_h_lo [B_ * L_ * H_];   // residual lo
__device__ bf16 g_hT_hi[B_ * H_ * L_];   // h transposed        [B][H][L]
__device__ bf16 g_hT_lo[B_ * H_ * L_];
__device__ bf16 g_WT_hi[H_ * H_];        // W^T (n=col-of-W rows)
__device__ bf16 g_WT_lo[H_ * H_];
__device__ bf16 g_G_hi [B_ * H_ * H_];   // G = h^T h (symmetric)
__device__ bf16 g_G_lo [B_ * H_ * H_];
__device__ bf16 g_MT_hi[B_ * H_ * H_];   // M^T = G W
__device__ bf16 g_MT_lo[B_ * H_ * H_];

// ---------------- helpers ---------------------------------------------------
__device__ __forceinline__ uint32_t smem_u32(const void* p) {
    uint32_t a;
    asm("{ .reg .u64 t; cvta.to.shared.u64 t, %1; cvt.u32.u64 %0, t; }" : "=r"(a) : "l"(p));
    return a;
}
__device__ __forceinline__ void cp16(uint32_t saddr, const void* gaddr) {
    asm volatile("cp.async.cg.shared.global [%0], [%1], 16;" :: "r"(saddr), "l"(gaddr));
}
__device__ __forceinline__ void cp_commit() {
    asm volatile("cp.async.commit_group;" ::: "memory");
}
__device__ __forceinline__ void cp_wait1() {
    asm volatile("cp.async.wait_group 1;" ::: "memory");
}
__device__ __forceinline__ void ldsm4(uint32_t* r, uint32_t addr) {
    asm volatile("ldmatrix.sync.aligned.m8n8.x4.shared.b16 {%0,%1,%2,%3}, [%4];"
                 : "=r"(r[0]), "=r"(r[1]), "=r"(r[2]), "=r"(r[3]) : "r"(addr));
}
__device__ __forceinline__ void mma16816(float* c, const uint32_t* a, const uint32_t* b) {
    asm volatile(
        "mma.sync.aligned.m16n8k16.row.col.f32.bf16.bf16.f32 "
        "{%0,%1,%2,%3}, {%4,%5,%6,%7}, {%8,%9}, {%0,%1,%2,%3};"
        : "+f"(c[0]), "+f"(c[1]), "+f"(c[2]), "+f"(c[3])
        : "r"(a[0]), "r"(a[1]), "r"(a[2]), "r"(a[3]), "r"(b[0]), "r"(b[1]));
}

// ---------------- RoPE + bf16 split ----------------------------------------
__global__ void rope_split(const float* __restrict__ x,
                           const float* __restrict__ cs,
                           const float* __restrict__ sn,
                           bf16* __restrict__ hh, bf16* __restrict__ hl) {
    long e = ((long)blockIdx.x * blockDim.x + threadIdx.x) * 4;
    int c = (int)(e & (H_ - 1));
    int l = (int)((e >> 10) & (L_ - 1));

    float4 xv = *(const float4*)(x + e);
    float4 cv = *(const float4*)(cs + (long)l * H_ + c);
    float4 sv = *(const float4*)(sn + (long)l * H_ + c);
    float4 rv;
    if (c < H_ / 2) {
        float4 t = *(const float4*)(x + e + H_ / 2);
        rv.x = -t.x; rv.y = -t.y; rv.z = -t.z; rv.w = -t.w;
    } else {
        rv = *(const float4*)(x + e - H_ / 2);
    }
    float o[4];
    o[0] = xv.x * cv.x + rv.x * sv.x;
    o[1] = xv.y * cv.y + rv.y * sv.y;
    o[2] = xv.z * cv.z + rv.z * sv.z;
    o[3] = xv.w * cv.w + rv.w * sv.w;

    bf16 hi[4], lo[4];
#pragma unroll
    for (int i = 0; i < 4; i++) {
        hi[i] = __float2bfloat16_rn(o[i]);
        lo[i] = __float2bfloat16_rn(o[i] - __bfloat162float(hi[i]));
    }
    ((__nv_bfloat162*)(hh + e))[0] = __nv_bfloat162(hi[0], hi[1]);
    ((__nv_bfloat162*)(hh + e))[1] = __nv_bfloat162(hi[2], hi[3]);
    ((__nv_bfloat162*)(hl + e))[0] = __nv_bfloat162(lo[0], lo[1]);
    ((__nv_bfloat162*)(hl + e))[1] = __nv_bfloat162(lo[2], lo[3]);
}

// ---------------- bf16 transpose [L][H] -> [H][L] ---------------------------
__global__ void transpose_bf16(const bf16* __restrict__ in_h, const bf16* __restrict__ in_l,
                               bf16* __restrict__ out_h, bf16* __restrict__ out_l) {
    __shared__ bf16 t[32][33];
    int z = blockIdx.z;
    int b = z >> 1, sel = z & 1;
    const bf16* in  = (sel ? in_l : in_h)   + (long)b * L_ * H_;
    bf16*       out = (sel ? out_l : out_h) + (long)b * L_ * H_;
    int l0 = blockIdx.x * 32, h0 = blockIdx.y * 32;
    int tx = threadIdx.x, ty = threadIdx.y;
#pragma unroll
    for (int i = 0; i < 4; i++)
        t[ty + 8 * i][tx] = in[(long)(l0 + ty + 8 * i) * H_ + h0 + tx];
    __syncthreads();
#pragma unroll
    for (int i = 0; i < 4; i++)
        out[(long)(h0 + ty + 8 * i) * L_ + l0 + tx] = t[tx][ty + 8 * i];
}

// ---------------- W split + transpose --------------------------------------
__global__ void wsplit_t(const float* __restrict__ W, bf16* __restrict__ wth,
                         bf16* __restrict__ wtl) {
    long e = (long)blockIdx.x * blockDim.x + threadIdx.x;
    int o = (int)(e >> 10), c = (int)(e & (H_ - 1));
    float v = W[e];
    bf16 hi = __float2bfloat16_rn(v);
    bf16 lo = __float2bfloat16_rn(v - __bfloat162float(hi));
    wth[(long)c * H_ + o] = hi;   // wth[n][k] = W[k][n]
    wtl[(long)c * H_ + o] = lo;
}

// ---------------- HMMA split-bf16 GEMM --------------------------------------
// C[m][n] = sum_k A[m][k]*B[n][k] with split accumulation
//   acc += Ah*Bh + Ah*Bl + Al*Bh   (lo*lo dropped, ~2^-18)
// CTA tile 128x128, BK=32, 8 warps (warp tile 32x64), 3-stage cp.async.
#define PITCH    80                       // bytes per smem row (32 bf16 + 8 pad)
#define TILE_B   (128 * PITCH)            // 10240 B per operand tile
#define STAGE_B  (4 * TILE_B)             // Ah, Al, Bh, Bl
#define NSTAGE   3
#define SMEM_BYTES (NSTAGE * STAGE_B)     // 122880

__global__ __launch_bounds__(256, 1)
void gemm_mma(const bf16* __restrict__ Ah, const bf16* __restrict__ Al,
              const bf16* __restrict__ Bh, const bf16* __restrict__ Bl,
              float* __restrict__ Cf, bf16* __restrict__ Ch, bf16* __restrict__ Cl,
              int K, int lda, int ldb, int ldc,
              long sA, long sB, long sC, int split_out) {
    extern __shared__ char sm[];
    const uint32_t sb = smem_u32(sm);

    const int tid  = threadIdx.x;
    const int wid  = tid >> 5;
    const int lane = tid & 31;
    const int bz   = blockIdx.z;
    const long m0  = (long)blockIdx.y * 128;
    const long n0  = (long)blockIdx.x * 128;

    const int warp_m = (wid >> 1) * 32;
    const int warp_n = (wid & 1) * 64;

    // per-thread cp.async assignment: 8 chunks of 16B
    const bf16* gbase[4];
    gbase[0] = Ah + bz * sA + m0 * lda;
    gbase[1] = Al + bz * sA + m0 * lda;
    gbase[2] = Bh + bz * sB + n0 * ldb;
    gbase[3] = Bl + bz * sB + n0 * ldb;

    int  c_tile[8], c_row[8], c_c[8];
    long c_goff[8];
    uint32_t c_soff[8];
#pragma unroll
    for (int i = 0; i < 8; i++) {
        int t = tid + i * 256;
        int tile = t >> 9;             // 0..3
        int row  = (t >> 2) & 127;
        int c    = t & 3;
        int ld   = (tile < 2) ? lda : ldb;
        c_tile[i] = tile;
        c_row[i]  = row;
        c_c[i]    = c;
        c_goff[i] = (long)row * ld + c * 8;
        c_soff[i] = (uint32_t)(tile * TILE_B + row * PITCH + c * 16);
    }

    auto load_stage = [&](int it) {
        int st = it % NSTAGE;
        long k0 = (long)it * 32;
        uint32_t sbase = sb + st * STAGE_B;
#pragma unroll
        for (int i = 0; i < 8; i++)
            cp16(sbase + c_soff[i], gbase[c_tile[i]] + k0 + c_goff[i]);
        cp_commit();
    };

    float acc[2][8][4];
#pragma unroll
    for (int mt = 0; mt < 2; mt++)
#pragma unroll
        for (int j = 0; j < 8; j++)
#pragma unroll
            for (int q = 0; q < 4; q++) acc[mt][j][q] = 0.f;

    const int nIter = K >> 5;
    load_stage(0);
    load_stage(1);

    // ldmatrix lane addressing (constants per thread)
    const int a_rowoff = (lane & 7) + ((lane >> 3) & 1) * 8;   // within 16-row tile
    const int a_choff  = (lane >> 4);                          // chunk +0/+1
    const int b_rowoff = ((lane >> 4) & 1) * 8 + (lane & 7);   // within 16 n-rows
    const int b_choff  = ((lane >> 3) & 1);

    for (int it = 0; it < nIter; it++) {
        cp_wait1();
        __syncthreads();
        if (it + 2 < nIter) load_stage(it + 2);

        uint32_t sbase = sb + (it % NSTAGE) * STAGE_B;
        uint32_t sAh = sbase;
        uint32_t sAl = sbase + TILE_B;
        uint32_t sBh = sbase + 2 * TILE_B;
        uint32_t sBl = sbase + 3 * TILE_B;

#pragma unroll
        for (int ks = 0; ks < 2; ks++) {
            int kc = ks * 2;
            uint32_t ah[2][4], al[2][4];
#pragma unroll
            for (int mt = 0; mt < 2; mt++) {
                uint32_t off = (uint32_t)((warp_m + mt * 16 + a_rowoff) * PITCH
                                          + (kc + a_choff) * 16);
                ldsm4(ah[mt], sAh + off);
                ldsm4(al[mt], sAl + off);
            }
#pragma unroll
            for (int j = 0; j < 8; j += 2) {
                uint32_t bh[4], bl[4];
                uint32_t off = (uint32_t)((warp_n + j * 8 + b_rowoff) * PITCH
                                          + (kc + b_choff) * 16);
                ldsm4(bh, sBh + off);
                ldsm4(bl, sBl + off);
#pragma unroll
                for (int mt = 0; mt < 2; mt++) {
                    mma16816(acc[mt][j],     ah[mt], bh);
                    mma16816(acc[mt][j],     ah[mt], bl);
                    mma16816(acc[mt][j],     al[mt], bh);
                    mma16816(acc[mt][j + 1], ah[mt], bh + 2);
                    mma16816(acc[mt][j + 1], ah[mt], bl + 2);
                    mma16816(acc[mt][j + 1], al[mt], bh + 2);
                }
            }
        }
    }

    // ---------------- epilogue ----------------
    const int r_lo = lane >> 2;           // row within 16-tile
    const int c_lo = 2 * (lane & 3);      // col pair within 8-tile
#pragma unroll
    for (int mt = 0; mt < 2; mt++) {
#pragma unroll
        for (int j = 0; j < 8; j++) {
            long row = m0 + warp_m + mt * 16 + r_lo;
            long col = n0 + warp_n + j * 8 + c_lo;
            float v0 = acc[mt][j][0], v1 = acc[mt][j][1];
            float v2 = acc[mt][j][2], v3 = acc[mt][j][3];
            if (!split_out) {
                float* p = Cf + bz * sC;
                *(float2*)(p + row * ldc + col)       = make_float2(v0, v1);
                *(float2*)(p + (row + 8) * ldc + col) = make_float2(v2, v3);
            } else {
                bf16 h0 = __float2bfloat16_rn(v0);
                bf16 h1 = __float2bfloat16_rn(v1);
                bf16 h2 = __float2bfloat16_rn(v2);
                bf16 h3 = __float2bfloat16_rn(v3);
                bf16 l0 = __float2bfloat16_rn(v0 - __bfloat162float(h0));
                bf16 l1 = __float2bfloat16_rn(v1 - __bfloat162float(h1));
                bf16 l2 = __float2bfloat16_rn(v2 - __bfloat162float(h2));
                bf16 l3 = __float2bfloat16_rn(v3 - __bfloat162float(h3));
                long o0 = bz * sC + row * ldc + col;
                long o1 = bz * sC + (row + 8) * ldc + col;
                *(__nv_bfloat162*)(Ch + o0) = __nv_bfloat162(h0, h1);
                *(__nv_bfloat162*)(Ch + o1) = __nv_bfloat162(h2, h3);
                *(__nv_bfloat162*)(Cl + o0) = __nv_bfloat162(l0, l1);
                *(__nv_bfloat162*)(Cl + o1) = __nv_bfloat162(l2, l3);
            }
        }
    }
}

// ---------------- launch ----------------------------------------------------
extern "C" void kernel_launch(void* const* d_in, const int* in_sizes, int n_in,
                              void* d_out, int out_size) {
    const float* x  = (const float*)d_in[0];
    const float* W  = (const float*)d_in[1];
    const float* cs = (const float*)d_in[2];
    const float* sn = (const float*)d_in[3];
    float* out = (float*)d_out;

    void *p0, *p1, *p2, *p3, *p4, *p5, *p6, *p7, *p8, *p9;
    cudaGetSymbolAddress(&p0, g_h_hi);  cudaGetSymbolAddress(&p1, g_h_lo);
    cudaGetSymbolAddress(&p2, g_hT_hi); cudaGetSymbolAddress(&p3, g_hT_lo);
    cudaGetSymbolAddress(&p4, g_WT_hi); cudaGetSymbolAddress(&p5, g_WT_lo);
    cudaGetSymbolAddress(&p6, g_G_hi);  cudaGetSymbolAddress(&p7, g_G_lo);
    cudaGetSymbolAddress(&p8, g_MT_hi); cudaGetSymbolAddress(&p9, g_MT_lo);
    bf16 *hh = (bf16*)p0, *hl = (bf16*)p1, *hth = (bf16*)p2, *htl = (bf16*)p3;
    bf16 *wth = (bf16*)p4, *wtl = (bf16*)p5, *Gh = (bf16*)p6, *Gl = (bf16*)p7;
    bf16 *MTh = (bf16*)p8, *MTl = (bf16*)p9;

    cudaFuncSetAttribute(gemm_mma, cudaFuncAttributeMaxDynamicSharedMemorySize,
                         SMEM_BYTES);

    const long HL = (long)H_ * L_;
    const long HH = (long)H_ * H_;

    // 1) RoPE + split
    rope_split<<<(B_ * L_ * H_ / 4) / 256, 256>>>(x, cs, sn, hh, hl);

    // 2) transpose h -> hT (hi & lo)
    transpose_bf16<<<dim3(L_ / 32, H_ / 32, B_ * 2), dim3(32, 8)>>>(hh, hl, hth, htl);

    // 3) W split + transpose
    wsplit_t<<<(H_ * H_) / 256, 256>>>(W, wth, wtl);

    // 4) G = h^T h : A=B=hT [H][L], K=L -> G (bf16 split, symmetric)
    gemm_mma<<<dim3(H_ / 128, H_ / 128, B_), 256, SMEM_BYTES>>>(
        hth, htl, hth, htl, nullptr, Gh, Gl, L_, L_, L_, H_, HL, HL, HH, 1);

    // 5) M^T = G W : A=G [H][H], B=W^T [n][k], K=H -> MT (bf16 split)
    gemm_mma<<<dim3(H_ / 128, H_ / 128, B_), 256, SMEM_BYTES>>>(
        Gh, Gl, wth, wtl, nullptr, MTh, MTl, H_, H_, H_, H_, HH, 0, HH, 1);

    // 6) out = h M : A=h [L][H], B=MT [n][k], K=H -> fp32 out
    gemm_mma<<<dim3(H_ / 128, L_ / 128, B_), 256, SMEM_BYTES>>>(
        hh, hl, MTh, MTl, out, nullptr, nullptr, H_, H_, H_, H_, HL, HH, HL, 0);
}

// round 5
// speedup vs baseline: 2.6099x; 1.1252x over previous
#include <cuda_runtime.h>
#include <cuda_bf16.h>
#include <cstdint>

#define B_ 2
#define L_ 4096
#define H_ 1024

typedef __nv_bfloat16 bf16;

// ---------------- scratch (__device__ globals; no runtime alloc) ------------
__device__ bf16 g_h_hi [B_ * L_ * H_];   // RoPE'd h, bf16 hi   [B][L][H]
__device__ bf16 g_h_lo [B_ * L_ * H_];   // residual lo
__device__ bf16 g_hT_hi[B_ * H_ * L_];   // h transposed        [B][H][L]
__device__ bf16 g_hT_lo[B_ * H_ * L_];
__device__ bf16 g_WT_hi[H_ * H_];        // W^T (rows = cols of W)
__device__ bf16 g_WT_lo[H_ * H_];
__device__ bf16 g_G_hi [B_ * H_ * H_];   // G = h^T h (symmetric)
__device__ bf16 g_G_lo [B_ * H_ * H_];
__device__ bf16 g_MT_hi[B_ * H_ * H_];   // M^T = G W
__device__ bf16 g_MT_lo[B_ * H_ * H_];

// ---------------- helpers ---------------------------------------------------
__device__ __forceinline__ uint32_t smem_u32(const void* p) {
    uint32_t a;
    asm("{ .reg .u64 t; cvta.to.shared.u64 t, %1; cvt.u32.u64 %0, t; }" : "=r"(a) : "l"(p));
    return a;
}
__device__ __forceinline__ void cp16(uint32_t saddr, const void* gaddr) {
    asm volatile("cp.async.cg.shared.global [%0], [%1], 16;" :: "r"(saddr), "l"(gaddr));
}
__device__ __forceinline__ void cp_commit() {
    asm volatile("cp.async.commit_group;" ::: "memory");
}
__device__ __forceinline__ void cp_wait1() {
    asm volatile("cp.async.wait_group 1;" ::: "memory");
}
__device__ __forceinline__ void ldsm4(uint32_t* r, uint32_t addr) {
    asm volatile("ldmatrix.sync.aligned.m8n8.x4.shared.b16 {%0,%1,%2,%3}, [%4];"
                 : "=r"(r[0]), "=r"(r[1]), "=r"(r[2]), "=r"(r[3]) : "r"(addr));
}
__device__ __forceinline__ void mma16816(float* c, const uint32_t* a, const uint32_t* b) {
    asm volatile(
        "mma.sync.aligned.m16n8k16.row.col.f32.bf16.bf16.f32 "
        "{%0,%1,%2,%3}, {%4,%5,%6,%7}, {%8,%9}, {%0,%1,%2,%3};"
        : "+f"(c[0]), "+f"(c[1]), "+f"(c[2]), "+f"(c[3])
        : "r"(a[0]), "r"(a[1]), "r"(a[2]), "r"(a[3]), "r"(b[0]), "r"(b[1]));
}

// ---------------- RoPE + bf16 split ----------------------------------------
__global__ void rope_split(const float* __restrict__ x,
                           const float* __restrict__ cs,
                           const float* __restrict__ sn,
                           bf16* __restrict__ hh, bf16* __restrict__ hl) {
    long e = ((long)blockIdx.x * blockDim.x + threadIdx.x) * 4;
    int c = (int)(e & (H_ - 1));
    int l = (int)((e >> 10) & (L_ - 1));

    float4 xv = *(const float4*)(x + e);
    float4 cv = *(const float4*)(cs + (long)l * H_ + c);
    float4 sv = *(const float4*)(sn + (long)l * H_ + c);
    float4 rv;
    if (c < H_ / 2) {
        float4 t = *(const float4*)(x + e + H_ / 2);
        rv.x = -t.x; rv.y = -t.y; rv.z = -t.z; rv.w = -t.w;
    } else {
        rv = *(const float4*)(x + e - H_ / 2);
    }
    float o[4];
    o[0] = xv.x * cv.x + rv.x * sv.x;
    o[1] = xv.y * cv.y + rv.y * sv.y;
    o[2] = xv.z * cv.z + rv.z * sv.z;
    o[3] = xv.w * cv.w + rv.w * sv.w;

    bf16 hi[4], lo[4];
#pragma unroll
    for (int i = 0; i < 4; i++) {
        hi[i] = __float2bfloat16_rn(o[i]);
        lo[i] = __float2bfloat16_rn(o[i] - __bfloat162float(hi[i]));
    }
    ((__nv_bfloat162*)(hh + e))[0] = __nv_bfloat162(hi[0], hi[1]);
    ((__nv_bfloat162*)(hh + e))[1] = __nv_bfloat162(hi[2], hi[3]);
    ((__nv_bfloat162*)(hl + e))[0] = __nv_bfloat162(lo[0], lo[1]);
    ((__nv_bfloat162*)(hl + e))[1] = __nv_bfloat162(lo[2], lo[3]);
}

// ---------------- bf16 transpose [L][H] -> [H][L] ---------------------------
__global__ void transpose_bf16(const bf16* __restrict__ in_h, const bf16* __restrict__ in_l,
                               bf16* __restrict__ out_h, bf16* __restrict__ out_l) {
    __shared__ bf16 t[32][33];
    int z = blockIdx.z;
    int b = z >> 1, sel = z & 1;
    const bf16* in  = (sel ? in_l : in_h)   + (long)b * L_ * H_;
    bf16*       out = (sel ? out_l : out_h) + (long)b * L_ * H_;
    int l0 = blockIdx.x * 32, h0 = blockIdx.y * 32;
    int tx = threadIdx.x, ty = threadIdx.y;
#pragma unroll
    for (int i = 0; i < 4; i++)
        t[ty + 8 * i][tx] = in[(long)(l0 + ty + 8 * i) * H_ + h0 + tx];
    __syncthreads();
#pragma unroll
    for (int i = 0; i < 4; i++)
        out[(long)(h0 + ty + 8 * i) * L_ + l0 + tx] = t[tx][ty + 8 * i];
}

// ---------------- W split + transpose --------------------------------------
__global__ void wsplit_t(const float* __restrict__ W, bf16* __restrict__ wth,
                         bf16* __restrict__ wtl) {
    long e = (long)blockIdx.x * blockDim.x + threadIdx.x;
    int o = (int)(e >> 10), c = (int)(e & (H_ - 1));
    float v = W[e];
    bf16 hi = __float2bfloat16_rn(v);
    bf16 lo = __float2bfloat16_rn(v - __bfloat162float(hi));
    wth[(long)c * H_ + o] = hi;   // wth[n][k] = W[k][n]
    wtl[(long)c * H_ + o] = lo;
}

// ---------------- HMMA split-bf16 GEMM --------------------------------------
// C[m][n] = sum_k A[m][k]*B[n][k] with split accumulation
//   acc += Ah*Bh + Ah*Bl + Al*Bh   (lo*lo dropped, ~2^-18)
// CTA tile 128x128, BK=64, 8 warps (warp tile 32x64), 3-stage cp.async.
// MMA issue order spreads same-accumulator reuse 32 issues apart (no RAW stall).
#define PITCH    144                      // bytes per smem row (64 bf16 + 16 pad)
#define TILE_B   (128 * PITCH)            // 18432 B per operand tile
#define STAGE_B  (4 * TILE_B)             // Ah, Al, Bh, Bl = 73728 B
#define NSTAGE   3
#define SMEM_BYTES (NSTAGE * STAGE_B)     // 221184 B

__global__ __launch_bounds__(256, 1)
void gemm_mma(const bf16* __restrict__ Ah, const bf16* __restrict__ Al,
              const bf16* __restrict__ Bh, const bf16* __restrict__ Bl,
              float* __restrict__ Cf, bf16* __restrict__ Ch, bf16* __restrict__ Cl,
              int K, int lda, int ldb, int ldc,
              long sA, long sB, long sC, int split_out) {
    extern __shared__ char sm[];
    const uint32_t sb = smem_u32(sm);

    const int tid  = threadIdx.x;
    const int wid  = tid >> 5;
    const int lane = tid & 31;
    const int bz   = blockIdx.z;
    const long m0  = (long)blockIdx.y * 128;
    const long n0  = (long)blockIdx.x * 128;

    const int warp_m = (wid >> 1) * 32;
    const int warp_n = (wid & 1) * 64;

    const bf16* gbase[4];
    gbase[0] = Ah + bz * sA + m0 * lda;
    gbase[1] = Al + bz * sA + m0 * lda;
    gbase[2] = Bh + bz * sB + n0 * ldb;
    gbase[3] = Bl + bz * sB + n0 * ldb;

    // per-thread cp.async mapping: 16 chunks of 16B per stage
    long c_goff[16];
    uint32_t c_soff[16];
    int c_tile[16];
#pragma unroll
    for (int i = 0; i < 16; i++) {
        int t = tid + i * 256;
        int tile = t >> 10;            // 1024 16B-chunks per tile
        int row  = (t >> 3) & 127;
        int c    = t & 7;
        int ld   = (tile < 2) ? lda : ldb;
        c_tile[i] = tile;
        c_goff[i] = (long)row * ld + c * 8;
        c_soff[i] = (uint32_t)(tile * TILE_B + row * PITCH + c * 16);
    }

    auto load_stage = [&](int it) {
        int st = it % NSTAGE;
        long k0 = (long)it * 64;
        uint32_t sbase = sb + st * STAGE_B;
#pragma unroll
        for (int i = 0; i < 16; i++)
            cp16(sbase + c_soff[i], gbase[c_tile[i]] + k0 + c_goff[i]);
        cp_commit();
    };

    float acc[2][8][4];
#pragma unroll
    for (int mt = 0; mt < 2; mt++)
#pragma unroll
        for (int j = 0; j < 8; j++)
#pragma unroll
            for (int q = 0; q < 4; q++) acc[mt][j][q] = 0.f;

    const int nIter = K >> 6;
    load_stage(0);
    load_stage(1);

    const int a_rowoff = (lane & 7) + ((lane >> 3) & 1) * 8;
    const int a_choff  = (lane >> 4);
    const int b_rowoff = ((lane >> 4) & 1) * 8 + (lane & 7);
    const int b_choff  = ((lane >> 3) & 1);

    for (int it = 0; it < nIter; it++) {
        cp_wait1();
        __syncthreads();
        if (it + 2 < nIter) load_stage(it + 2);

        uint32_t sbase = sb + (it % NSTAGE) * STAGE_B;
        uint32_t sAh = sbase;
        uint32_t sAl = sbase + TILE_B;
        uint32_t sBh = sbase + 2 * TILE_B;
        uint32_t sBl = sbase + 3 * TILE_B;

#pragma unroll
        for (int ks = 0; ks < 4; ks++) {
            const int kc = ks * 2;
            uint32_t ah[2][4], al[2][4], bh[4][4], bl[4][4];
#pragma unroll
            for (int mt = 0; mt < 2; mt++) {
                uint32_t off = (uint32_t)((warp_m + mt * 16 + a_rowoff) * PITCH
                                          + (kc + a_choff) * 16);
                ldsm4(ah[mt], sAh + off);
                ldsm4(al[mt], sAl + off);
            }
#pragma unroll
            for (int jp = 0; jp < 4; jp++) {
                uint32_t off = (uint32_t)((warp_n + jp * 16 + b_rowoff) * PITCH
                                          + (kc + b_choff) * 16);
                ldsm4(bh[jp], sBh + off);
                ldsm4(bl[jp], sBl + off);
            }
            // 96 MMAs; same accumulator reused only every 32 issues.
#pragma unroll
            for (int p = 0; p < 3; p++) {
#pragma unroll
                for (int jp = 0; jp < 4; jp++) {
#pragma unroll
                    for (int mt = 0; mt < 2; mt++) {
                        const uint32_t* av = (p == 2) ? al[mt] : ah[mt];
                        const uint32_t* bv = (p == 1) ? bl[jp] : bh[jp];
                        mma16816(acc[mt][2 * jp],     av, bv);
                        mma16816(acc[mt][2 * jp + 1], av, bv + 2);
                    }
                }
            }
        }
    }

    // ---------------- epilogue ----------------
    const int r_lo = lane >> 2;
    const int c_lo = 2 * (lane & 3);
#pragma unroll
    for (int mt = 0; mt < 2; mt++) {
#pragma unroll
        for (int j = 0; j < 8; j++) {
            long row = m0 + warp_m + mt * 16 + r_lo;
            long col = n0 + warp_n + j * 8 + c_lo;
            float v0 = acc[mt][j][0], v1 = acc[mt][j][1];
            float v2 = acc[mt][j][2], v3 = acc[mt][j][3];
            if (!split_out) {
                float* p = Cf + bz * sC;
                *(float2*)(p + row * ldc + col)       = make_float2(v0, v1);
                *(float2*)(p + (row + 8) * ldc + col) = make_float2(v2, v3);
            } else {
                bf16 h0 = __float2bfloat16_rn(v0);
                bf16 h1 = __float2bfloat16_rn(v1);
                bf16 h2 = __float2bfloat16_rn(v2);
                bf16 h3 = __float2bfloat16_rn(v3);
                bf16 l0 = __float2bfloat16_rn(v0 - __bfloat162float(h0));
                bf16 l1 = __float2bfloat16_rn(v1 - __bfloat162float(h1));
                bf16 l2 = __float2bfloat16_rn(v2 - __bfloat162float(h2));
                bf16 l3 = __float2bfloat16_rn(v3 - __bfloat162float(h3));
                long o0 = bz * sC + row * ldc + col;
                long o1 = bz * sC + (row + 8) * ldc + col;
                *(__nv_bfloat162*)(Ch + o0) = __nv_bfloat162(h0, h1);
                *(__nv_bfloat162*)(Ch + o1) = __nv_bfloat162(h2, h3);
                *(__nv_bfloat162*)(Cl + o0) = __nv_bfloat162(l0, l1);
                *(__nv_bfloat162*)(Cl + o1) = __nv_bfloat162(l2, l3);
            }
        }
    }
}

// ---------------- launch ----------------------------------------------------
extern "C" void kernel_launch(void* const* d_in, const int* in_sizes, int n_in,
                              void* d_out, int out_size) {
    const float* x  = (const float*)d_in[0];
    const float* W  = (const float*)d_in[1];
    const float* cs = (const float*)d_in[2];
    const float* sn = (const float*)d_in[3];
    float* out = (float*)d_out;

    void *p0, *p1, *p2, *p3, *p4, *p5, *p6, *p7, *p8, *p9;
    cudaGetSymbolAddress(&p0, g_h_hi);  cudaGetSymbolAddress(&p1, g_h_lo);
    cudaGetSymbolAddress(&p2, g_hT_hi); cudaGetSymbolAddress(&p3, g_hT_lo);
    cudaGetSymbolAddress(&p4, g_WT_hi); cudaGetSymbolAddress(&p5, g_WT_lo);
    cudaGetSymbolAddress(&p6, g_G_hi);  cudaGetSymbolAddress(&p7, g_G_lo);
    cudaGetSymbolAddress(&p8, g_MT_hi); cudaGetSymbolAddress(&p9, g_MT_lo);
    bf16 *hh = (bf16*)p0, *hl = (bf16*)p1, *hth = (bf16*)p2, *htl = (bf16*)p3;
    bf16 *wth = (bf16*)p4, *wtl = (bf16*)p5, *Gh = (bf16*)p6, *Gl = (bf16*)p7;
    bf16 *MTh = (bf16*)p8, *MTl = (bf16*)p9;

    cudaFuncSetAttribute(gemm_mma, cudaFuncAttributeMaxDynamicSharedMemorySize,
                         SMEM_BYTES);

    const long HL = (long)H_ * L_;
    const long HH = (long)H_ * H_;

    // 1) RoPE + split
    rope_split<<<(B_ * L_ * H_ / 4) / 256, 256>>>(x, cs, sn, hh, hl);

    // 2) transpose h -> hT (hi & lo)
    transpose_bf16<<<dim3(L_ / 32, H_ / 32, B_ * 2), dim3(32, 8)>>>(hh, hl, hth, htl);

    // 3) W split + transpose
    wsplit_t<<<(H_ * H_) / 256, 256>>>(W, wth, wtl);

    // 4) G = h^T h : A=B=hT [H][L], K=L -> G (bf16 split, symmetric)
    gemm_mma<<<dim3(H_ / 128, H_ / 128, B_), 256, SMEM_BYTES>>>(
        hth, htl, hth, htl, nullptr, Gh, Gl, L_, L_, L_, H_, HL, HL, HH, 1);

    // 5) M^T = G W : A=G [H][H], B=W^T [n][k], K=H -> MT (bf16 split)
    gemm_mma<<<dim3(H_ / 128, H_ / 128, B_), 256, SMEM_BYTES>>>(
        Gh, Gl, wth, wtl, nullptr, MTh, MTl, H_, H_, H_, H_, HH, 0, HH, 1);

    // 6) out = h M : A=h [L][H], B=MT [n][k], K=H -> fp32 out
    gemm_mma<<<dim3(H_ / 128, L_ / 128, B_), 256, SMEM_BYTES>>>(
        hh, hl, MTh, MTl, out, nullptr, nullptr, H_, H_, H_, H_, HL, HH, HL, 0);
}

// round 6
// speedup vs baseline: 2.7038x; 1.0360x over previous
#include <cuda_runtime.h>
#include <cuda_bf16.h>
#include <cstdint>

#define B_ 2
#define L_ 4096
#define H_ 1024

typedef __nv_bfloat16 bf16;

// ---------------- scratch (__device__ globals; no runtime alloc) ------------
__device__ bf16 g_h_hi [B_ * L_ * H_];   // RoPE'd h, bf16 hi   [B][L][H]
__device__ bf16 g_h_lo [B_ * L_ * H_];   // residual lo
__device__ bf16 g_hT_hi[B_ * H_ * L_];   // h transposed        [B][H][L]
__device__ bf16 g_hT_lo[B_ * H_ * L_];
__device__ bf16 g_WT_hi[H_ * H_];        // W^T (rows = cols of W)
__device__ bf16 g_WT_lo[H_ * H_];
__device__ bf16 g_G_hi [B_ * H_ * H_];   // G = h^T h (symmetric)
__device__ bf16 g_G_lo [B_ * H_ * H_];
__device__ bf16 g_MT_hi[B_ * H_ * H_];   // M^T = G W
__device__ bf16 g_MT_lo[B_ * H_ * H_];

// ---------------- helpers ---------------------------------------------------
__device__ __forceinline__ uint32_t smem_u32(const void* p) {
    uint32_t a;
    asm("{ .reg .u64 t; cvta.to.shared.u64 t, %1; cvt.u32.u64 %0, t; }" : "=r"(a) : "l"(p));
    return a;
}
__device__ __forceinline__ void cp16(uint32_t saddr, const void* gaddr) {
    asm volatile("cp.async.cg.shared.global [%0], [%1], 16;" :: "r"(saddr), "l"(gaddr));
}
__device__ __forceinline__ void cp_commit() {
    asm volatile("cp.async.commit_group;" ::: "memory");
}
__device__ __forceinline__ void cp_wait1() {
    asm volatile("cp.async.wait_group 1;" ::: "memory");
}
__device__ __forceinline__ void ldsm4(uint32_t* r, uint32_t addr) {
    asm volatile("ldmatrix.sync.aligned.m8n8.x4.shared.b16 {%0,%1,%2,%3}, [%4];"
                 : "=r"(r[0]), "=r"(r[1]), "=r"(r[2]), "=r"(r[3]) : "r"(addr));
}
__device__ __forceinline__ void mma16816(float* c, const uint32_t* a, const uint32_t* b) {
    asm volatile(
        "mma.sync.aligned.m16n8k16.row.col.f32.bf16.bf16.f32 "
        "{%0,%1,%2,%3}, {%4,%5,%6,%7}, {%8,%9}, {%0,%1,%2,%3};"
        : "+f"(c[0]), "+f"(c[1]), "+f"(c[2]), "+f"(c[3])
        : "r"(a[0]), "r"(a[1]), "r"(a[2]), "r"(a[3]), "r"(b[0]), "r"(b[1]));
}

// ---------------- RoPE + bf16 split ----------------------------------------
__global__ void rope_split(const float* __restrict__ x,
                           const float* __restrict__ cs,
                           const float* __restrict__ sn,
                           bf16* __restrict__ hh, bf16* __restrict__ hl) {
    long e = ((long)blockIdx.x * blockDim.x + threadIdx.x) * 4;
    int c = (int)(e & (H_ - 1));
    int l = (int)((e >> 10) & (L_ - 1));

    float4 xv = *(const float4*)(x + e);
    float4 cv = *(const float4*)(cs + (long)l * H_ + c);
    float4 sv = *(const float4*)(sn + (long)l * H_ + c);
    float4 rv;
    if (c < H_ / 2) {
        float4 t = *(const float4*)(x + e + H_ / 2);
        rv.x = -t.x; rv.y = -t.y; rv.z = -t.z; rv.w = -t.w;
    } else {
        rv = *(const float4*)(x + e - H_ / 2);
    }
    float o[4];
    o[0] = xv.x * cv.x + rv.x * sv.x;
    o[1] = xv.y * cv.y + rv.y * sv.y;
    o[2] = xv.z * cv.z + rv.z * sv.z;
    o[3] = xv.w * cv.w + rv.w * sv.w;

    bf16 hi[4], lo[4];
#pragma unroll
    for (int i = 0; i < 4; i++) {
        hi[i] = __float2bfloat16_rn(o[i]);
        lo[i] = __float2bfloat16_rn(o[i] - __bfloat162float(hi[i]));
    }
    ((__nv_bfloat162*)(hh + e))[0] = __nv_bfloat162(hi[0], hi[1]);
    ((__nv_bfloat162*)(hh + e))[1] = __nv_bfloat162(hi[2], hi[3]);
    ((__nv_bfloat162*)(hl + e))[0] = __nv_bfloat162(lo[0], lo[1]);
    ((__nv_bfloat162*)(hl + e))[1] = __nv_bfloat162(lo[2], lo[3]);
}

// ---------------- bf16 transpose [L][H] -> [H][L], vectorized 64x64 ---------
__global__ void transpose_bf16(const bf16* __restrict__ in_h, const bf16* __restrict__ in_l,
                               bf16* __restrict__ out_h, bf16* __restrict__ out_l) {
    __shared__ bf16 t[64][66];
    int z = blockIdx.z;
    int b = z >> 1, sel = z & 1;
    const bf16* in  = (sel ? in_l : in_h)   + (long)b * L_ * H_;
    bf16*       out = (sel ? out_l : out_h) + (long)b * L_ * H_;
    int l0 = blockIdx.x * 64, h0 = blockIdx.y * 64;
    int tx = threadIdx.x, ty = threadIdx.y;   // 32 x 8

#pragma unroll
    for (int i = 0; i < 8; i++) {
        int r = ty + 8 * i;
        __nv_bfloat162 v = *(const __nv_bfloat162*)(in + (long)(l0 + r) * H_ + h0 + 2 * tx);
        t[r][2 * tx]     = v.x;
        t[r][2 * tx + 1] = v.y;
    }
    __syncthreads();
#pragma unroll
    for (int i = 0; i < 8; i++) {
        int r = ty + 8 * i;                   // h-row within tile
        __nv_bfloat162 v(t[2 * tx][r], t[2 * tx + 1][r]);
        *(__nv_bfloat162*)(out + (long)(h0 + r) * L_ + l0 + 2 * tx) = v;
    }
}

// ---------------- W split + transpose --------------------------------------
__global__ void wsplit_t(const float* __restrict__ W, bf16* __restrict__ wth,
                         bf16* __restrict__ wtl) {
    long e = (long)blockIdx.x * blockDim.x + threadIdx.x;
    int o = (int)(e >> 10), c = (int)(e & (H_ - 1));
    float v = W[e];
    bf16 hi = __float2bfloat16_rn(v);
    bf16 lo = __float2bfloat16_rn(v - __bfloat162float(hi));
    wth[(long)c * H_ + o] = hi;   // wth[n][k] = W[k][n]
    wtl[(long)c * H_ + o] = lo;
}

// ---------------- HMMA split-bf16 GEMM --------------------------------------
// C[m][n] = sum_k A[m][k]*B[n][k] with split accumulation
//   acc += Ah*Bh + Ah*Bl + Al*Bh   (lo*lo dropped, ~2^-18)
// CTA tile 128x128, BK=64, 16 warps (warp tile 32x32), 3-stage cp.async.
#define PITCH    144                      // bytes per smem row (64 bf16 + 16 pad)
#define TILE_B   (128 * PITCH)            // 18432 B per operand tile
#define STAGE_B  (4 * TILE_B)             // Ah, Al, Bh, Bl = 73728 B
#define NSTAGE   3
#define SMEM_BYTES (NSTAGE * STAGE_B)     // 221184 B

__global__ __launch_bounds__(512, 1)
void gemm_mma(const bf16* __restrict__ Ah, const bf16* __restrict__ Al,
              const bf16* __restrict__ Bh, const bf16* __restrict__ Bl,
              float* __restrict__ Cf, bf16* __restrict__ Ch, bf16* __restrict__ Cl,
              int K, int lda, int ldb, int ldc,
              long sA, long sB, long sC, int split_out) {
    extern __shared__ char sm[];
    const uint32_t sb = smem_u32(sm);

    const int tid  = threadIdx.x;
    const int wid  = tid >> 5;
    const int lane = tid & 31;
    const int bz   = blockIdx.z;
    const long m0  = (long)blockIdx.y * 128;
    const long n0  = (long)blockIdx.x * 128;

    const int warp_m = (wid >> 2) * 32;       // 4 m-groups
    const int warp_n = (wid & 3) * 32;        // 4 n-groups

    const bf16* gbase[4];
    gbase[0] = Ah + bz * sA + m0 * lda;
    gbase[1] = Al + bz * sA + m0 * lda;
    gbase[2] = Bh + bz * sB + n0 * ldb;
    gbase[3] = Bl + bz * sB + n0 * ldb;

    // per-thread cp.async mapping: 8 chunks of 16B per stage (512 thr * 8 = 4096)
    long c_goff[8];
    uint32_t c_soff[8];
    int c_tile[8];
#pragma unroll
    for (int i = 0; i < 8; i++) {
        int t = tid + i * 512;
        int tile = t >> 10;            // 1024 16B-chunks per tile
        int row  = (t >> 3) & 127;
        int c    = t & 7;
        int ld   = (tile < 2) ? lda : ldb;
        c_tile[i] = tile;
        c_goff[i] = (long)row * ld + c * 8;
        c_soff[i] = (uint32_t)(tile * TILE_B + row * PITCH + c * 16);
    }

    auto load_stage = [&](int it) {
        int st = it % NSTAGE;
        long k0 = (long)it * 64;
        uint32_t sbase = sb + st * STAGE_B;
#pragma unroll
        for (int i = 0; i < 8; i++)
            cp16(sbase + c_soff[i], gbase[c_tile[i]] + k0 + c_goff[i]);
        cp_commit();
    };

    float acc[2][4][4];
#pragma unroll
    for (int mt = 0; mt < 2; mt++)
#pragma unroll
        for (int j = 0; j < 4; j++)
#pragma unroll
            for (int q = 0; q < 4; q++) acc[mt][j][q] = 0.f;

    const int nIter = K >> 6;
    load_stage(0);
    load_stage(1);

    const int a_rowoff = (lane & 7) + ((lane >> 3) & 1) * 8;
    const int a_choff  = (lane >> 4);
    const int b_rowoff = ((lane >> 4) & 1) * 8 + (lane & 7);
    const int b_choff  = ((lane >> 3) & 1);

    for (int it = 0; it < nIter; it++) {
        cp_wait1();
        __syncthreads();
        if (it + 2 < nIter) load_stage(it + 2);

        uint32_t sbase = sb + (it % NSTAGE) * STAGE_B;
        uint32_t sAh = sbase;
        uint32_t sAl = sbase + TILE_B;
        uint32_t sBh = sbase + 2 * TILE_B;
        uint32_t sBl = sbase + 3 * TILE_B;

#pragma unroll
        for (int ks = 0; ks < 4; ks++) {
            const int kc = ks * 2;
            uint32_t ah[2][4], al[2][4], bh[2][4], bl[2][4];
#pragma unroll
            for (int mt = 0; mt < 2; mt++) {
                uint32_t off = (uint32_t)((warp_m + mt * 16 + a_rowoff) * PITCH
                                          + (kc + a_choff) * 16);
                ldsm4(ah[mt], sAh + off);
                ldsm4(al[mt], sAl + off);
            }
#pragma unroll
            for (int jp = 0; jp < 2; jp++) {
                uint32_t off = (uint32_t)((warp_n + jp * 16 + b_rowoff) * PITCH
                                          + (kc + b_choff) * 16);
                ldsm4(bh[jp], sBh + off);
                ldsm4(bl[jp], sBl + off);
            }
            // 24 MMAs; same accumulator reused every 8 issues.
#pragma unroll
            for (int p = 0; p < 3; p++) {
#pragma unroll
                for (int jp = 0; jp < 2; jp++) {
#pragma unroll
                    for (int mt = 0; mt < 2; mt++) {
                        const uint32_t* av = (p == 2) ? al[mt] : ah[mt];
                        const uint32_t* bv = (p == 1) ? bl[jp] : bh[jp];
                        mma16816(acc[mt][2 * jp],     av, bv);
                        mma16816(acc[mt][2 * jp + 1], av, bv + 2);
                    }
                }
            }
        }
    }

    // ---------------- epilogue ----------------
    const int r_lo = lane >> 2;
    const int c_lo = 2 * (lane & 3);
#pragma unroll
    for (int mt = 0; mt < 2; mt++) {
#pragma unroll
        for (int j = 0; j < 4; j++) {
            long row = m0 + warp_m + mt * 16 + r_lo;
            long col = n0 + warp_n + j * 8 + c_lo;
            float v0 = acc[mt][j][0], v1 = acc[mt][j][1];
            float v2 = acc[mt][j][2], v3 = acc[mt][j][3];
            if (!split_out) {
                float* p = Cf + bz * sC;
                *(float2*)(p + row * ldc + col)       = make_float2(v0, v1);
                *(float2*)(p + (row + 8) * ldc + col) = make_float2(v2, v3);
            } else {
                bf16 h0 = __float2bfloat16_rn(v0);
                bf16 h1 = __float2bfloat16_rn(v1);
                bf16 h2 = __float2bfloat16_rn(v2);
                bf16 h3 = __float2bfloat16_rn(v3);
                bf16 l0 = __float2bfloat16_rn(v0 - __bfloat162float(h0));
                bf16 l1 = __float2bfloat16_rn(v1 - __bfloat162float(h1));
                bf16 l2 = __float2bfloat16_rn(v2 - __bfloat162float(h2));
                bf16 l3 = __float2bfloat16_rn(v3 - __bfloat162float(h3));
                long o0 = bz * sC + row * ldc + col;
                long o1 = bz * sC + (row + 8) * ldc + col;
                *(__nv_bfloat162*)(Ch + o0) = __nv_bfloat162(h0, h1);
                *(__nv_bfloat162*)(Ch + o1) = __nv_bfloat162(h2, h3);
                *(__nv_bfloat162*)(Cl + o0) = __nv_bfloat162(l0, l1);
                *(__nv_bfloat162*)(Cl + o1) = __nv_bfloat162(l2, l3);
            }
        }
    }
}

// ---------------- launch ----------------------------------------------------
extern "C" void kernel_launch(void* const* d_in, const int* in_sizes, int n_in,
                              void* d_out, int out_size) {
    const float* x  = (const float*)d_in[0];
    const float* W  = (const float*)d_in[1];
    const float* cs = (const float*)d_in[2];
    const float* sn = (const float*)d_in[3];
    float* out = (float*)d_out;

    void *p0, *p1, *p2, *p3, *p4, *p5, *p6, *p7, *p8, *p9;
    cudaGetSymbolAddress(&p0, g_h_hi);  cudaGetSymbolAddress(&p1, g_h_lo);
    cudaGetSymbolAddress(&p2, g_hT_hi); cudaGetSymbolAddress(&p3, g_hT_lo);
    cudaGetSymbolAddress(&p4, g_WT_hi); cudaGetSymbolAddress(&p5, g_WT_lo);
    cudaGetSymbolAddress(&p6, g_G_hi);  cudaGetSymbolAddress(&p7, g_G_lo);
    cudaGetSymbolAddress(&p8, g_MT_hi); cudaGetSymbolAddress(&p9, g_MT_lo);
    bf16 *hh = (bf16*)p0, *hl = (bf16*)p1, *hth = (bf16*)p2, *htl = (bf16*)p3;
    bf16 *wth = (bf16*)p4, *wtl = (bf16*)p5, *Gh = (bf16*)p6, *Gl = (bf16*)p7;
    bf16 *MTh = (bf16*)p8, *MTl = (bf16*)p9;

    cudaFuncSetAttribute(gemm_mma, cudaFuncAttributeMaxDynamicSharedMemorySize,
                         SMEM_BYTES);

    const long HL = (long)H_ * L_;
    const long HH = (long)H_ * H_;

    // 1) RoPE + split
    rope_split<<<(B_ * L_ * H_ / 4) / 256, 256>>>(x, cs, sn, hh, hl);

    // 2) transpose h -> hT (hi & lo)
    transpose_bf16<<<dim3(L_ / 64, H_ / 64, B_ * 2), dim3(32, 8)>>>(hh, hl, hth, htl);

    // 3) W split + transpose
    wsplit_t<<<(H_ * H_) / 256, 256>>>(W, wth, wtl);

    // 4) G = h^T h : A=B=hT [H][L], K=L -> G (bf16 split, symmetric)
    gemm_mma<<<dim3(H_ / 128, H_ / 128, B_), 512, SMEM_BYTES>>>(
        hth, htl, hth, htl, nullptr, Gh, Gl, L_, L_, L_, H_, HL, HL, HH, 1);

    // 5) M^T = G W : A=G [H][H], B=W^T [n][k], K=H -> MT (bf16 split)
    gemm_mma<<<dim3(H_ / 128, H_ / 128, B_), 512, SMEM_BYTES>>>(
        Gh, Gl, wth, wtl, nullptr, MTh, MTl, H_, H_, H_, H_, HH, 0, HH, 1);

    // 6) out = h M : A=h [L][H], B=MT [n][k], K=H -> fp32 out
    gemm_mma<<<dim3(H_ / 128, L_ / 128, B_), 512, SMEM_BYTES>>>(
        hh, hl, MTh, MTl, out, nullptr, nullptr, H_, H_, H_, H_, HL, HH, HL, 0);
}